// round 3
// baseline (speedup 1.0000x reference)
#include <cuda_runtime.h>

#define DDIM   512
#define KLAT   64
#define NCODE  1024
#define ROWS   256      // rows per block
#define NTHR   256      // threads per block
#define KT     32       // k-tile for phase A
#define CT     128      // codes per tile for phase B
#define XS_STRIDE 260   // padded stride for transposed x tile
#define ZS_STRIDE 68    // padded stride for z tile (16B-aligned rows)

// Scratch: decoded codebook (codebook @ U_k^T) and per-code squared norms.
__device__ float g_dec[NCODE * DDIM];
__device__ float g_csq[NCODE];

// Prep: g_dec[c][d] = sum_k codebook[c][k] * U[d][k];  g_csq[c] = ||codebook[c]||^2
__global__ void prep_kernel(const float* __restrict__ U, const float* __restrict__ cb) {
    __shared__ float code[KLAT];
    const int c = blockIdx.x;
    const int tid = threadIdx.x;   // 128 threads
    if (tid < KLAT / 4)
        ((float4*)code)[tid] = ((const float4*)(cb + c * KLAT))[tid];
    __syncthreads();
    if (tid == 0) {
        float s = 0.f;
        #pragma unroll
        for (int k = 0; k < KLAT; k++) s = fmaf(code[k], code[k], s);
        g_csq[c] = s;
    }
    #pragma unroll
    for (int i = 0; i < 4; i++) {
        const int d = tid + i * 128;
        const float4* u4 = (const float4*)(U + d * KLAT);
        float s = 0.f;
        #pragma unroll
        for (int q = 0; q < KLAT / 4; q++) {
            float4 u = u4[q];
            float4 cv = ((const float4*)code)[q];
            s = fmaf(u.x, cv.x, s);
            s = fmaf(u.y, cv.y, s);
            s = fmaf(u.z, cv.z, s);
            s = fmaf(u.w, cv.w, s);
        }
        g_dec[c * DDIM + d] = s;
    }
}

// Fused: z = x@U (phase A), VQ argmin (phase B), all outputs (phase C).
__global__ void __launch_bounds__(NTHR, 1)
vqvae_main(const float* __restrict__ x,
           const float* __restrict__ U,
           const float* __restrict__ cb,
           float* __restrict__ out,
           int B)
{
    extern __shared__ float sm[];
    float* zs   = sm;                           // ROWS * ZS_STRIDE
    float* xa   = sm + ROWS * ZS_STRIDE;        // overlaid scratch region
    float* xs_t = xa;                           // KT * XS_STRIDE   (phase A)
    float* us   = xa + KT * XS_STRIDE;          // KT * 64          (phase A)
    float* cs   = xa;                           // CT * 64          (phase B)
    float* csq  = xa + CT * 64;                 // CT               (phase B)

    const int tid = threadIdx.x;
    const int R0  = blockIdx.x * ROWS;
    const int ty  = tid >> 3;                   // 0..31 -> rows ty*8..+7
    const int tx  = tid & 7;                    // 0..7  -> cols tx*8..+7

    // ---------------- Phase A: z tile = x_tile @ U ----------------
    float acc[8][8];
    #pragma unroll
    for (int i = 0; i < 8; i++)
        #pragma unroll
        for (int j = 0; j < 8; j++) acc[i][j] = 0.f;

    const float4* x4 = (const float4*)x;
    const float4* U4 = (const float4*)U;

    for (int kk = 0; kk < DDIM; kk += KT) {
        // x tile: coalesced float4 loads, stored transposed (k-major)
        #pragma unroll
        for (int j = 0; j < 8; j++) {
            int l4  = j * NTHR + tid;           // 0..2047
            int row = l4 >> 3;                  // 0..255
            int k4  = l4 & 7;                   // 0..7
            float4 v = x4[(size_t)(R0 + row) * (DDIM / 4) + (kk >> 2) + k4];
            xs_t[(4 * k4 + 0) * XS_STRIDE + row] = v.x;
            xs_t[(4 * k4 + 1) * XS_STRIDE + row] = v.y;
            xs_t[(4 * k4 + 2) * XS_STRIDE + row] = v.z;
            xs_t[(4 * k4 + 3) * XS_STRIDE + row] = v.w;
        }
        // U tile
        #pragma unroll
        for (int j = 0; j < 2; j++) {
            int l4 = j * NTHR + tid;            // 0..511
            int kr = l4 >> 4;                   // 0..31
            int c4 = l4 & 15;                   // 0..15
            ((float4*)us)[kr * 16 + c4] = U4[(kk + kr) * 16 + c4];
        }
        __syncthreads();
        #pragma unroll
        for (int k = 0; k < KT; k++) {
            float4 a0 = *(const float4*)&xs_t[k * XS_STRIDE + ty * 8];
            float4 a1 = *(const float4*)&xs_t[k * XS_STRIDE + ty * 8 + 4];
            float4 b0 = *(const float4*)&us[k * 64 + tx * 8];
            float4 b1 = *(const float4*)&us[k * 64 + tx * 8 + 4];
            float a[8] = {a0.x, a0.y, a0.z, a0.w, a1.x, a1.y, a1.z, a1.w};
            float b[8] = {b0.x, b0.y, b0.z, b0.w, b1.x, b1.y, b1.z, b1.w};
            #pragma unroll
            for (int i = 0; i < 8; i++)
                #pragma unroll
                for (int j = 0; j < 8; j++)
                    acc[i][j] = fmaf(a[i], b[j], acc[i][j]);
        }
        __syncthreads();
    }
    // write z tile to shared
    #pragma unroll
    for (int i = 0; i < 8; i++) {
        int row = ty * 8 + i;
        #pragma unroll
        for (int j = 0; j < 8; j++)
            zs[row * ZS_STRIDE + tx * 8 + j] = acc[i][j];
    }
    __syncthreads();

    // ---------------- Phase B: argmin_c (c_sq - 2 z.c), thread = row ----------------
    float zr[64];
    {
        const float4* zrow = (const float4*)&zs[tid * ZS_STRIDE];
        #pragma unroll
        for (int q = 0; q < 16; q++) {
            float4 v = zrow[q];
            zr[4 * q + 0] = v.x; zr[4 * q + 1] = v.y;
            zr[4 * q + 2] = v.z; zr[4 * q + 3] = v.w;
        }
    }
    float best = 3.4e38f;
    int   bidx = 0;
    for (int c0 = 0; c0 < NCODE; c0 += CT) {
        #pragma unroll
        for (int j = 0; j < 8; j++) {
            int l4 = j * NTHR + tid;            // 0..2047 float4s of tile
            ((float4*)cs)[l4] = ((const float4*)cb)[c0 * (KLAT / 4) + l4];
        }
        if (tid < CT) csq[tid] = g_csq[c0 + tid];
        __syncthreads();
        for (int c = 0; c < CT; c++) {
            const float4* cr = (const float4*)&cs[c * KLAT];
            float d0 = 0.f, d1 = 0.f, d2 = 0.f, d3 = 0.f;
            #pragma unroll
            for (int q = 0; q < 16; q++) {
                float4 cv = cr[q];              // broadcast LDS.128
                d0 = fmaf(zr[4 * q + 0], cv.x, d0);
                d1 = fmaf(zr[4 * q + 1], cv.y, d1);
                d2 = fmaf(zr[4 * q + 2], cv.z, d2);
                d3 = fmaf(zr[4 * q + 3], cv.w, d3);
            }
            float dot = (d0 + d1) + (d2 + d3);
            float score = fmaf(-2.f, dot, csq[c]);
            if (score < best) { best = score; bidx = c0 + c; }  // strict <: first-min ties
        }
        __syncthreads();
    }

    // ---------------- Phase C: outputs [x_recon | z | z_q_ste | indices] ----------------
    const size_t Z_OFF   = (size_t)B * DDIM;
    const size_t ZQ_OFF  = Z_OFF + (size_t)B * KLAT;
    const size_t IDX_OFF = ZQ_OFF + (size_t)B * KLAT;

    out[IDX_OFF + R0 + tid] = (float)bidx;

    // z output, fully coalesced float4
    {
        float4* oz = (float4*)(out + Z_OFF);
        #pragma unroll
        for (int j = 0; j < 16; j++) {
            int l4  = j * NTHR + tid;           // 0..4095
            int row = l4 >> 4;
            int c4  = l4 & 15;
            float4 v = *(const float4*)&zs[row * ZS_STRIDE + 4 * c4];
            oz[(size_t)(R0 + row) * 16 + c4] = v;
        }
    }

    // warp-cooperative z_q_ste + x_recon writes (coalesced per row)
    const int w = tid >> 5, lane = tid & 31;
    const float2* cb2  = (const float2*)cb;
    const float4* dec4 = (const float4*)g_dec;
    float2* ozq = (float2*)(out + ZQ_OFF);
    float4* ox  = (float4*)out;
    for (int r = 0; r < 32; r++) {
        int row = w * 32 + r;
        int idx = __shfl_sync(0xffffffffu, bidx, r);
        float2 zv = *(const float2*)&zs[row * ZS_STRIDE + 2 * lane];
        float2 cv = cb2[(size_t)idx * (KLAT / 2) + lane];
        float2 o;
        o.x = zv.x + (cv.x - zv.x);             // STE numerics: z + (z_q - z)
        o.y = zv.y + (cv.y - zv.y);
        ozq[(size_t)(R0 + row) * (KLAT / 2) + lane] = o;
        #pragma unroll
        for (int j = 0; j < 4; j++)
            ox[(size_t)(R0 + row) * (DDIM / 4) + j * 32 + lane] =
                dec4[(size_t)idx * (DDIM / 4) + j * 32 + lane];
    }
}

extern "C" void kernel_launch(void* const* d_in, const int* in_sizes, int n_in,
                              void* d_out, int out_size) {
    // Identify inputs by element count (robust to metadata ordering):
    // U_k = 512*64 = 32768, codebook = 1024*64 = 65536, x = B*512 (the rest).
    const float *x = 0, *U = 0, *cb = 0;
    int xsize = 0;
    for (int i = 0; i < n_in; i++) {
        if (in_sizes[i] == DDIM * KLAT)       U  = (const float*)d_in[i];
        else if (in_sizes[i] == NCODE * KLAT) cb = (const float*)d_in[i];
        else { x = (const float*)d_in[i]; xsize = in_sizes[i]; }
    }
    float* out = (float*)d_out;
    const int B = xsize / DDIM;

    const int smem_bytes = (ROWS * ZS_STRIDE + KT * XS_STRIDE + KT * 64) * (int)sizeof(float);
    cudaFuncSetAttribute(vqvae_main, cudaFuncAttributeMaxDynamicSharedMemorySize, smem_bytes);

    prep_kernel<<<NCODE, 128>>>(U, cb);
    vqvae_main<<<B / ROWS, NTHR, smem_bytes>>>(x, U, cb, out, B);
}

// round 4
// speedup vs baseline: 1.2527x; 1.2527x over previous
#include <cuda_runtime.h>

#define DDIM   512
#define KLAT   64
#define NCODE  1024
#define ROWS   256      // rows per block
#define NTHR   256      // threads per block
#define KT     32       // k-tile for phase A
#define CN     64       // codes per tile for phase B
#define XS_STRIDE 260   // padded stride for transposed x tile (phase A)
#define ZS_STRIDE 68    // padded stride for z tile, row-major (phase C)
#define ZT_STRIDE 260   // padded stride for z tile, transposed (phase B)
#define CS_STRIDE 68    // padded stride for transposed code tile (phase B)

// Scratch: decoded codebook (codebook @ U_k^T) and per-code squared norms.
__device__ float g_dec[NCODE * DDIM];
__device__ float g_csq[NCODE];

// Prep: g_dec[c][d] = sum_k codebook[c][k] * U[d][k];  g_csq[c] = ||codebook[c]||^2
__global__ void prep_kernel(const float* __restrict__ U, const float* __restrict__ cb) {
    __shared__ float code[KLAT];
    const int c = blockIdx.x;
    const int tid = threadIdx.x;   // 128 threads
    if (tid < KLAT / 4)
        ((float4*)code)[tid] = ((const float4*)(cb + c * KLAT))[tid];
    __syncthreads();
    if (tid == 0) {
        float s = 0.f;
        #pragma unroll
        for (int k = 0; k < KLAT; k++) s = fmaf(code[k], code[k], s);
        g_csq[c] = s;
    }
    #pragma unroll
    for (int i = 0; i < 4; i++) {
        const int d = tid + i * 128;
        const float4* u4 = (const float4*)(U + d * KLAT);
        float s = 0.f;
        #pragma unroll
        for (int q = 0; q < KLAT / 4; q++) {
            float4 u = u4[q];
            float4 cv = ((const float4*)code)[q];
            s = fmaf(u.x, cv.x, s);
            s = fmaf(u.y, cv.y, s);
            s = fmaf(u.z, cv.z, s);
            s = fmaf(u.w, cv.w, s);
        }
        g_dec[c * DDIM + d] = s;
    }
}

// Shared memory layout (floats):
//   zs   [0, 17408)              z row-major (phase C)
//   zt   [17408, 34048)          z transposed [k][row] (phase B A-operand)
//   cs   [34048, 38400)          code tile transposed [k][code] (phase B B-operand)
//   csq  [38400, 38464)
//   sidx [38464, 38720)          per-row argmin result (int)
//   phase A scratch (xs_t, us) overlays zt.
#define SM_ZS   0
#define SM_ZT   17408
#define SM_CS   34048
#define SM_CSQ  38400
#define SM_SIDX 38464
#define SM_TOTAL 38720

__global__ void __launch_bounds__(NTHR, 1)
vqvae_main(const float* __restrict__ x,
           const float* __restrict__ U,
           const float* __restrict__ cb,
           float* __restrict__ out,
           int B)
{
    extern __shared__ float sm[];
    float* zs    = sm + SM_ZS;
    float* zt    = sm + SM_ZT;
    float* cs    = sm + SM_CS;
    float* csq_s = sm + SM_CSQ;
    int*   sidx  = (int*)(sm + SM_SIDX);
    float* xs_t  = zt;                       // phase A overlay (KT*XS_STRIDE = 8320)
    float* us    = zt + KT * XS_STRIDE;      // phase A overlay (KT*64 = 2048) <= 16640 total

    const int tid = threadIdx.x;
    const int R0  = blockIdx.x * ROWS;
    const int ty  = tid >> 3;                // 0..31 -> rows ty*8..+7
    const int tx  = tid & 7;                 // 0..7  -> cols tx*8..+7

    // ---------------- Phase A: z tile = x_tile @ U ----------------
    float acc[8][8];
    #pragma unroll
    for (int i = 0; i < 8; i++)
        #pragma unroll
        for (int j = 0; j < 8; j++) acc[i][j] = 0.f;

    const float4* x4 = (const float4*)x;
    const float4* U4 = (const float4*)U;

    for (int kk = 0; kk < DDIM; kk += KT) {
        #pragma unroll
        for (int j = 0; j < 8; j++) {
            int l4  = j * NTHR + tid;        // 0..2047
            int row = l4 >> 3;               // 0..255
            int k4  = l4 & 7;                // 0..7
            float4 v = x4[(size_t)(R0 + row) * (DDIM / 4) + (kk >> 2) + k4];
            xs_t[(4 * k4 + 0) * XS_STRIDE + row] = v.x;
            xs_t[(4 * k4 + 1) * XS_STRIDE + row] = v.y;
            xs_t[(4 * k4 + 2) * XS_STRIDE + row] = v.z;
            xs_t[(4 * k4 + 3) * XS_STRIDE + row] = v.w;
        }
        #pragma unroll
        for (int j = 0; j < 2; j++) {
            int l4 = j * NTHR + tid;         // 0..511
            int kr = l4 >> 4;                // 0..31
            int c4 = l4 & 15;                // 0..15
            ((float4*)us)[kr * 16 + c4] = U4[(kk + kr) * 16 + c4];
        }
        __syncthreads();
        #pragma unroll
        for (int k = 0; k < KT; k++) {
            float4 a0 = *(const float4*)&xs_t[k * XS_STRIDE + ty * 8];
            float4 a1 = *(const float4*)&xs_t[k * XS_STRIDE + ty * 8 + 4];
            float4 b0 = *(const float4*)&us[k * 64 + tx * 8];
            float4 b1 = *(const float4*)&us[k * 64 + tx * 8 + 4];
            float a[8] = {a0.x, a0.y, a0.z, a0.w, a1.x, a1.y, a1.z, a1.w};
            float b[8] = {b0.x, b0.y, b0.z, b0.w, b1.x, b1.y, b1.z, b1.w};
            #pragma unroll
            for (int i = 0; i < 8; i++)
                #pragma unroll
                for (int j = 0; j < 8; j++)
                    acc[i][j] = fmaf(a[i], b[j], acc[i][j]);
        }
        __syncthreads();
    }

    // Write z both row-major (zs, for phase C) and transposed (zt, for phase B).
    // Safe: xs_t/us overlay zt, and all reads of them finished at the last sync.
    #pragma unroll
    for (int i = 0; i < 8; i++) {
        int row = ty * 8 + i;
        #pragma unroll
        for (int j = 0; j < 8; j++) {
            float v = acc[i][j];
            zs[row * ZS_STRIDE + tx * 8 + j] = v;
            zt[(tx * 8 + j) * ZT_STRIDE + row] = v;
        }
    }
    __syncthreads();

    // ---------------- Phase B: scores = z @ cb^T as 8x8 register-tiled GEMM ----------------
    // Thread (ty,tx): rows ty*8+i, codes (ct + tx*8 + j). Running argmin per row.
    float best[8];
    int   bidx[8];
    #pragma unroll
    for (int i = 0; i < 8; i++) { best[i] = 3.4e38f; bidx[i] = 0; }

    const float4* cb4 = (const float4*)cb;

    for (int ct = 0; ct < NCODE; ct += CN) {
        // Load code tile transposed: cb[ct+c][k] -> cs[k][c]
        #pragma unroll
        for (int j = 0; j < 4; j++) {
            int l4 = j * NTHR + tid;         // 0..1023
            int c  = l4 >> 4;                // 0..63
            int k4 = l4 & 15;                // 0..15
            float4 v = cb4[(size_t)(ct + c) * 16 + k4];
            cs[(4 * k4 + 0) * CS_STRIDE + c] = v.x;
            cs[(4 * k4 + 1) * CS_STRIDE + c] = v.y;
            cs[(4 * k4 + 2) * CS_STRIDE + c] = v.z;
            cs[(4 * k4 + 3) * CS_STRIDE + c] = v.w;
        }
        if (tid < CN) csq_s[tid] = g_csq[ct + tid];
        __syncthreads();

        float dot[8][8];
        #pragma unroll
        for (int i = 0; i < 8; i++)
            #pragma unroll
            for (int j = 0; j < 8; j++) dot[i][j] = 0.f;

        #pragma unroll 4
        for (int k = 0; k < KLAT; k++) {
            float4 a0 = *(const float4*)&zt[k * ZT_STRIDE + ty * 8];
            float4 a1 = *(const float4*)&zt[k * ZT_STRIDE + ty * 8 + 4];
            float4 b0 = *(const float4*)&cs[k * CS_STRIDE + tx * 8];
            float4 b1 = *(const float4*)&cs[k * CS_STRIDE + tx * 8 + 4];
            float a[8] = {a0.x, a0.y, a0.z, a0.w, a1.x, a1.y, a1.z, a1.w};
            float b[8] = {b0.x, b0.y, b0.z, b0.w, b1.x, b1.y, b1.z, b1.w};
            #pragma unroll
            for (int i = 0; i < 8; i++)
                #pragma unroll
                for (int j = 0; j < 8; j++)
                    dot[i][j] = fmaf(a[i], b[j], dot[i][j]);
        }

        // score = csq - 2*dot; running first-min per row (thread-local codes ascending)
        #pragma unroll
        for (int j = 0; j < 8; j++) {
            float cq  = csq_s[tx * 8 + j];
            int  code = ct + tx * 8 + j;
            #pragma unroll
            for (int i = 0; i < 8; i++) {
                float s = fmaf(-2.f, dot[i][j], cq);
                if (s < best[i]) { best[i] = s; bidx[i] = code; }
            }
        }
        __syncthreads();
    }

    // Cross-tx reduction (8 consecutive lanes share ty); tie-break toward lower index.
    #pragma unroll
    for (int i = 0; i < 8; i++) {
        float s = best[i];
        int   ix = bidx[i];
        #pragma unroll
        for (int off = 4; off > 0; off >>= 1) {
            float s2 = __shfl_down_sync(0xffffffffu, s, off, 8);
            int  ix2 = __shfl_down_sync(0xffffffffu, ix, off, 8);
            if (s2 < s || (s2 == s && ix2 < ix)) { s = s2; ix = ix2; }
        }
        if (tx == 0) sidx[ty * 8 + i] = ix;
    }
    __syncthreads();

    // ---------------- Phase C: outputs [x_recon | z | z_q_ste | indices] ----------------
    const size_t Z_OFF   = (size_t)B * DDIM;
    const size_t ZQ_OFF  = Z_OFF + (size_t)B * KLAT;
    const size_t IDX_OFF = ZQ_OFF + (size_t)B * KLAT;

    out[IDX_OFF + R0 + tid] = (float)sidx[tid];

    // z output, fully coalesced float4
    {
        float4* oz = (float4*)(out + Z_OFF);
        #pragma unroll
        for (int j = 0; j < 16; j++) {
            int l4  = j * NTHR + tid;        // 0..4095
            int row = l4 >> 4;
            int c4  = l4 & 15;
            float4 v = *(const float4*)&zs[row * ZS_STRIDE + 4 * c4];
            oz[(size_t)(R0 + row) * 16 + c4] = v;
        }
    }

    // warp-cooperative z_q_ste + x_recon writes (coalesced per row)
    const int w = tid >> 5, lane = tid & 31;
    const float2* cb2  = (const float2*)cb;
    const float4* dec4 = (const float4*)g_dec;
    float2* ozq = (float2*)(out + ZQ_OFF);
    float4* ox  = (float4*)out;
    for (int r = 0; r < 32; r++) {
        int row = w * 32 + r;
        int idx = sidx[row];
        float2 zv = *(const float2*)&zs[row * ZS_STRIDE + 2 * lane];
        float2 cv = cb2[(size_t)idx * (KLAT / 2) + lane];
        float2 o;
        o.x = zv.x + (cv.x - zv.x);          // STE numerics: z + (z_q - z)
        o.y = zv.y + (cv.y - zv.y);
        ozq[(size_t)(R0 + row) * (KLAT / 2) + lane] = o;
        #pragma unroll
        for (int j = 0; j < 4; j++)
            ox[(size_t)(R0 + row) * (DDIM / 4) + j * 32 + lane] =
                dec4[(size_t)idx * (DDIM / 4) + j * 32 + lane];
    }
}

extern "C" void kernel_launch(void* const* d_in, const int* in_sizes, int n_in,
                              void* d_out, int out_size) {
    // Identify inputs by element count: U_k = 512*64, codebook = 1024*64, x = B*512.
    const float *x = 0, *U = 0, *cb = 0;
    int xsize = 0;
    for (int i = 0; i < n_in; i++) {
        if (in_sizes[i] == DDIM * KLAT)       U  = (const float*)d_in[i];
        else if (in_sizes[i] == NCODE * KLAT) cb = (const float*)d_in[i];
        else { x = (const float*)d_in[i]; xsize = in_sizes[i]; }
    }
    float* out = (float*)d_out;
    const int B = xsize / DDIM;

    const int smem_bytes = SM_TOTAL * (int)sizeof(float);
    cudaFuncSetAttribute(vqvae_main, cudaFuncAttributeMaxDynamicSharedMemorySize, smem_bytes);

    prep_kernel<<<NCODE, 128>>>(U, cb);
    vqvae_main<<<B / ROWS, NTHR, smem_bytes>>>(x, U, cb, out, B);
}

// round 5
// speedup vs baseline: 1.3149x; 1.0497x over previous
#include <cuda_runtime.h>

#define DDIM   512
#define KLAT   64
#define NCODE  1024
#define ROWS   256      // rows per block
#define NTHR   256      // threads per block
#define KT     32       // k-tile for phase A
#define CN     64       // codes per tile for phase B
#define XS_STRIDE 260   // padded stride for transposed x tile (phase A)
#define ZS_STRIDE 68    // padded stride for z tile, row-major (phase C)
#define ZT_STRIDE 260   // padded stride for z tile, transposed (phase B)
#define CS_STRIDE 68    // padded stride for transposed code tile (phase B)

// Scratch: decoded codebook (codebook @ U_k^T) and per-code squared norms.
__device__ float g_dec[NCODE * DDIM];
__device__ float g_csq[NCODE];

// ---- packed f32x2 helpers (Blackwell FFMA2 path, PTX-only) ----
typedef unsigned long long u64;
static __device__ __forceinline__ u64 pk2(float x, float y) {
    u64 r;
    asm("mov.b64 %0, {%1, %2};" : "=l"(r) : "f"(x), "f"(y));
    return r;
}
static __device__ __forceinline__ float2 upk2(u64 v) {
    float2 f;
    asm("mov.b64 {%0, %1}, %2;" : "=f"(f.x), "=f"(f.y) : "l"(v));
    return f;
}
static __device__ __forceinline__ void ffma2(u64 &d, u64 a, u64 b) {
    asm("fma.rn.f32x2 %0, %1, %2, %0;" : "+l"(d) : "l"(a), "l"(b));
}

// Prep: g_dec[c][d] = sum_k codebook[c][k] * U[d][k];  g_csq[c] = ||codebook[c]||^2
__global__ void prep_kernel(const float* __restrict__ U, const float* __restrict__ cb) {
    __shared__ float code[KLAT];
    const int c = blockIdx.x;
    const int tid = threadIdx.x;   // 128 threads
    if (tid < KLAT / 4)
        ((float4*)code)[tid] = ((const float4*)(cb + c * KLAT))[tid];
    __syncthreads();
    if (tid == 0) {
        float s = 0.f;
        #pragma unroll
        for (int k = 0; k < KLAT; k++) s = fmaf(code[k], code[k], s);
        g_csq[c] = s;
    }
    #pragma unroll
    for (int i = 0; i < 4; i++) {
        const int d = tid + i * 128;
        const float4* u4 = (const float4*)(U + d * KLAT);
        float s = 0.f;
        #pragma unroll
        for (int q = 0; q < KLAT / 4; q++) {
            float4 u = u4[q];
            float4 cv = ((const float4*)code)[q];
            s = fmaf(u.x, cv.x, s);
            s = fmaf(u.y, cv.y, s);
            s = fmaf(u.z, cv.z, s);
            s = fmaf(u.w, cv.w, s);
        }
        g_dec[c * DDIM + d] = s;
    }
}

// Shared memory layout (floats):
//   zs   [0, 17408)              z row-major (phase C)
//   zt   [17408, 34048)          z transposed [k][row] (phase B A-operand)
//   cs   [34048, 38400)          code tile transposed [k][code] (phase B B-operand)
//   csq  [38400, 38464)
//   sidx [38464, 38720)          per-row argmin result (int)
//   phase A scratch (xs_t, us) overlays zt.
#define SM_ZS   0
#define SM_ZT   17408
#define SM_CS   34048
#define SM_CSQ  38400
#define SM_SIDX 38464
#define SM_TOTAL 38720

__global__ void __launch_bounds__(NTHR, 1)
vqvae_main(const float* __restrict__ x,
           const float* __restrict__ U,
           const float* __restrict__ cb,
           float* __restrict__ out,
           int B)
{
    extern __shared__ float sm[];
    float* zs    = sm + SM_ZS;
    float* zt    = sm + SM_ZT;
    float* cs    = sm + SM_CS;
    float* csq_s = sm + SM_CSQ;
    int*   sidx  = (int*)(sm + SM_SIDX);
    float* xs_t  = zt;                       // phase A overlay (KT*XS_STRIDE = 8320)
    float* us    = zt + KT * XS_STRIDE;      // phase A overlay (KT*64 = 2048)

    const int tid = threadIdx.x;
    const int R0  = blockIdx.x * ROWS;
    const int ty  = tid >> 3;                // 0..31 -> rows ty*8..+7
    const int tx  = tid & 7;                 // 0..7  -> cols tx*8..+7

    // ---------------- Phase A: z tile = x_tile @ U (FFMA2) ----------------
    u64 acc2[8][4];                          // acc2[i][p] = (acc[i][2p], acc[i][2p+1])
    #pragma unroll
    for (int i = 0; i < 8; i++)
        #pragma unroll
        for (int p = 0; p < 4; p++) acc2[i][p] = 0ull;

    const float4* x4 = (const float4*)x;
    const float4* U4 = (const float4*)U;

    for (int kk = 0; kk < DDIM; kk += KT) {
        #pragma unroll
        for (int j = 0; j < 8; j++) {
            int l4  = j * NTHR + tid;        // 0..2047
            int row = l4 >> 3;               // 0..255
            int k4  = l4 & 7;                // 0..7
            float4 v = x4[(size_t)(R0 + row) * (DDIM / 4) + (kk >> 2) + k4];
            xs_t[(4 * k4 + 0) * XS_STRIDE + row] = v.x;
            xs_t[(4 * k4 + 1) * XS_STRIDE + row] = v.y;
            xs_t[(4 * k4 + 2) * XS_STRIDE + row] = v.z;
            xs_t[(4 * k4 + 3) * XS_STRIDE + row] = v.w;
        }
        #pragma unroll
        for (int j = 0; j < 2; j++) {
            int l4 = j * NTHR + tid;         // 0..511
            int kr = l4 >> 4;                // 0..31
            int c4 = l4 & 15;                // 0..15
            ((float4*)us)[kr * 16 + c4] = U4[(kk + kr) * 16 + c4];
        }
        __syncthreads();
        #pragma unroll
        for (int k = 0; k < KT; k++) {
            float4 a0 = *(const float4*)&xs_t[k * XS_STRIDE + ty * 8];
            float4 a1 = *(const float4*)&xs_t[k * XS_STRIDE + ty * 8 + 4];
            ulonglong2 b01 = *(const ulonglong2*)&us[k * 64 + tx * 8];
            ulonglong2 b23 = *(const ulonglong2*)&us[k * 64 + tx * 8 + 4];
            u64 bp[4] = {b01.x, b01.y, b23.x, b23.y};
            float a[8] = {a0.x, a0.y, a0.z, a0.w, a1.x, a1.y, a1.z, a1.w};
            #pragma unroll
            for (int i = 0; i < 8; i++) {
                u64 ad = pk2(a[i], a[i]);
                #pragma unroll
                for (int p = 0; p < 4; p++) ffma2(acc2[i][p], ad, bp[p]);
            }
        }
        __syncthreads();
    }

    // Write z both row-major (zs, for phase C) and transposed (zt, for phase B).
    #pragma unroll
    for (int i = 0; i < 8; i++) {
        int row = ty * 8 + i;
        #pragma unroll
        for (int p = 0; p < 4; p++) {
            float2 v = upk2(acc2[i][p]);
            zs[row * ZS_STRIDE + tx * 8 + 2 * p]     = v.x;
            zs[row * ZS_STRIDE + tx * 8 + 2 * p + 1] = v.y;
            zt[(tx * 8 + 2 * p)     * ZT_STRIDE + row] = v.x;
            zt[(tx * 8 + 2 * p + 1) * ZT_STRIDE + row] = v.y;
        }
    }
    __syncthreads();

    // ---------------- Phase B: scores = z @ cb^T, 8x8 register tile (FFMA2) ----------------
    float best[8];
    int   bidx[8];
    #pragma unroll
    for (int i = 0; i < 8; i++) { best[i] = 3.4e38f; bidx[i] = 0; }

    const float4* cb4 = (const float4*)cb;

    for (int ct = 0; ct < NCODE; ct += CN) {
        // Load code tile transposed: cb[ct+c][k] -> cs[k][c]
        #pragma unroll
        for (int j = 0; j < 4; j++) {
            int l4 = j * NTHR + tid;         // 0..1023
            int c  = l4 >> 4;                // 0..63
            int k4 = l4 & 15;                // 0..15
            float4 v = cb4[(size_t)(ct + c) * 16 + k4];
            cs[(4 * k4 + 0) * CS_STRIDE + c] = v.x;
            cs[(4 * k4 + 1) * CS_STRIDE + c] = v.y;
            cs[(4 * k4 + 2) * CS_STRIDE + c] = v.z;
            cs[(4 * k4 + 3) * CS_STRIDE + c] = v.w;
        }
        if (tid < CN) csq_s[tid] = g_csq[ct + tid];
        __syncthreads();

        u64 dot2[8][4];                      // dot2[i][p] = (dot[i][2p], dot[i][2p+1])
        #pragma unroll
        for (int i = 0; i < 8; i++)
            #pragma unroll
            for (int p = 0; p < 4; p++) dot2[i][p] = 0ull;

        #pragma unroll 4
        for (int k = 0; k < KLAT; k++) {
            float4 a0 = *(const float4*)&zt[k * ZT_STRIDE + ty * 8];
            float4 a1 = *(const float4*)&zt[k * ZT_STRIDE + ty * 8 + 4];
            ulonglong2 b01 = *(const ulonglong2*)&cs[k * CS_STRIDE + tx * 8];
            ulonglong2 b23 = *(const ulonglong2*)&cs[k * CS_STRIDE + tx * 8 + 4];
            u64 bp[4] = {b01.x, b01.y, b23.x, b23.y};
            float a[8] = {a0.x, a0.y, a0.z, a0.w, a1.x, a1.y, a1.z, a1.w};
            #pragma unroll
            for (int i = 0; i < 8; i++) {
                u64 ad = pk2(a[i], a[i]);
                #pragma unroll
                for (int p = 0; p < 4; p++) ffma2(dot2[i][p], ad, bp[p]);
            }
        }

        // score = csq - 2*dot; running first-min per row (thread-local codes ascending)
        #pragma unroll
        for (int p = 0; p < 4; p++) {
            float cq0 = csq_s[tx * 8 + 2 * p];
            float cq1 = csq_s[tx * 8 + 2 * p + 1];
            int code0 = ct + tx * 8 + 2 * p;
            #pragma unroll
            for (int i = 0; i < 8; i++) {
                float2 d = upk2(dot2[i][p]);
                float s0 = fmaf(-2.f, d.x, cq0);
                float s1 = fmaf(-2.f, d.y, cq1);
                if (s0 < best[i]) { best[i] = s0; bidx[i] = code0; }
                if (s1 < best[i]) { best[i] = s1; bidx[i] = code0 + 1; }
            }
        }
        __syncthreads();
    }

    // Cross-tx reduction (8 consecutive lanes share ty); tie-break toward lower index.
    #pragma unroll
    for (int i = 0; i < 8; i++) {
        float s = best[i];
        int   ix = bidx[i];
        #pragma unroll
        for (int off = 4; off > 0; off >>= 1) {
            float s2 = __shfl_down_sync(0xffffffffu, s, off, 8);
            int  ix2 = __shfl_down_sync(0xffffffffu, ix, off, 8);
            if (s2 < s || (s2 == s && ix2 < ix)) { s = s2; ix = ix2; }
        }
        if (tx == 0) sidx[ty * 8 + i] = ix;
    }
    __syncthreads();

    // ---------------- Phase C: outputs [x_recon | z | z_q_ste | indices] ----------------
    const size_t Z_OFF   = (size_t)B * DDIM;
    const size_t ZQ_OFF  = Z_OFF + (size_t)B * KLAT;
    const size_t IDX_OFF = ZQ_OFF + (size_t)B * KLAT;

    out[IDX_OFF + R0 + tid] = (float)sidx[tid];

    // z output, fully coalesced float4
    {
        float4* oz = (float4*)(out + Z_OFF);
        #pragma unroll
        for (int j = 0; j < 16; j++) {
            int l4  = j * NTHR + tid;        // 0..4095
            int row = l4 >> 4;
            int c4  = l4 & 15;
            float4 v = *(const float4*)&zs[row * ZS_STRIDE + 4 * c4];
            oz[(size_t)(R0 + row) * 16 + c4] = v;
        }
    }

    // warp-cooperative z_q_ste + x_recon writes (coalesced per row)
    const int w = tid >> 5, lane = tid & 31;
    const float2* cb2  = (const float2*)cb;
    const float4* dec4 = (const float4*)g_dec;
    float2* ozq = (float2*)(out + ZQ_OFF);
    float4* ox  = (float4*)out;
    for (int r = 0; r < 32; r++) {
        int row = w * 32 + r;
        int idx = sidx[row];
        float2 zv = *(const float2*)&zs[row * ZS_STRIDE + 2 * lane];
        float2 cv = cb2[(size_t)idx * (KLAT / 2) + lane];
        float2 o;
        o.x = zv.x + (cv.x - zv.x);          // STE numerics: z + (z_q - z)
        o.y = zv.y + (cv.y - zv.y);
        ozq[(size_t)(R0 + row) * (KLAT / 2) + lane] = o;
        #pragma unroll
        for (int j = 0; j < 4; j++)
            ox[(size_t)(R0 + row) * (DDIM / 4) + j * 32 + lane] =
                dec4[(size_t)idx * (DDIM / 4) + j * 32 + lane];
    }
}

extern "C" void kernel_launch(void* const* d_in, const int* in_sizes, int n_in,
                              void* d_out, int out_size) {
    // Identify inputs by element count: U_k = 512*64, codebook = 1024*64, x = B*512.
    const float *x = 0, *U = 0, *cb = 0;
    int xsize = 0;
    for (int i = 0; i < n_in; i++) {
        if (in_sizes[i] == DDIM * KLAT)       U  = (const float*)d_in[i];
        else if (in_sizes[i] == NCODE * KLAT) cb = (const float*)d_in[i];
        else { x = (const float*)d_in[i]; xsize = in_sizes[i]; }
    }
    float* out = (float*)d_out;
    const int B = xsize / DDIM;

    const int smem_bytes = SM_TOTAL * (int)sizeof(float);
    cudaFuncSetAttribute(vqvae_main, cudaFuncAttributeMaxDynamicSharedMemorySize, smem_bytes);

    prep_kernel<<<NCODE, 128>>>(U, cb);
    vqvae_main<<<B / ROWS, NTHR, smem_bytes>>>(x, U, cb, out, B);
}

// round 6
// speedup vs baseline: 1.6539x; 1.2577x over previous
#include <cuda_runtime.h>

#define DDIM   512
#define KLAT   64
#define NCODE  1024
#define ROWS   128      // rows per block
#define NTHR   128      // threads per block
#define KT     32       // k-tile for phase A
#define CN     64       // codes per tile for phase B
#define XS_STRIDE 132   // padded stride for transposed x tile (phase A overlay)
#define ZT_STRIDE 132   // padded stride for z tile, transposed [k][row]
#define CS_STRIDE 68    // padded stride for transposed code tile [k][code]

// Scratch: decoded codebook (codebook @ U_k^T) and per-code squared norms.
__device__ float g_dec[NCODE * DDIM];
__device__ float g_csq[NCODE];

// ---- packed f32x2 helpers (Blackwell FFMA2 path, PTX-only) ----
typedef unsigned long long u64;
static __device__ __forceinline__ u64 pk2(float x, float y) {
    u64 r;
    asm("mov.b64 %0, {%1, %2};" : "=l"(r) : "f"(x), "f"(y));
    return r;
}
static __device__ __forceinline__ float2 upk2(u64 v) {
    float2 f;
    asm("mov.b64 {%0, %1}, %2;" : "=f"(f.x), "=f"(f.y) : "l"(v));
    return f;
}
static __device__ __forceinline__ void ffma2(u64 &d, u64 a, u64 b) {
    asm("fma.rn.f32x2 %0, %1, %2, %0;" : "+l"(d) : "l"(a), "l"(b));
}

// Prep: g_dec[c][d] = sum_k codebook[c][k] * U[d][k];  g_csq[c] = ||codebook[c]||^2
__global__ void prep_kernel(const float* __restrict__ U, const float* __restrict__ cb) {
    __shared__ float code[KLAT];
    const int c = blockIdx.x;
    const int tid = threadIdx.x;   // 128 threads
    if (tid < KLAT / 4)
        ((float4*)code)[tid] = ((const float4*)(cb + c * KLAT))[tid];
    __syncthreads();
    if (tid == 0) {
        float s = 0.f;
        #pragma unroll
        for (int k = 0; k < KLAT; k++) s = fmaf(code[k], code[k], s);
        g_csq[c] = s;
    }
    #pragma unroll
    for (int i = 0; i < 4; i++) {
        const int d = tid + i * 128;
        const float4* u4 = (const float4*)(U + d * KLAT);
        float s = 0.f;
        #pragma unroll
        for (int q = 0; q < KLAT / 4; q++) {
            float4 u = u4[q];
            float4 cv = ((const float4*)code)[q];
            s = fmaf(u.x, cv.x, s);
            s = fmaf(u.y, cv.y, s);
            s = fmaf(u.z, cv.z, s);
            s = fmaf(u.w, cv.w, s);
        }
        g_dec[c * DDIM + d] = s;
    }
}

// Shared memory layout (floats):
//   zt   [0, 8448)        z transposed [k][row]  (phase A scratch overlays this)
//   cs   [8448, 12800)    code tile transposed [k][code]
//   csq  [12800, 12864)
//   sidx [12864, 12992)
#define SM_ZT   0
#define SM_CS   8448
#define SM_CSQ  12800
#define SM_SIDX 12864
#define SM_TOTAL 12992

__global__ void __launch_bounds__(NTHR, 3)
vqvae_main(const float* __restrict__ x,
           const float* __restrict__ U,
           const float* __restrict__ cb,
           float* __restrict__ out,
           int B)
{
    extern __shared__ float sm[];
    float* zt    = sm + SM_ZT;
    float* cs    = sm + SM_CS;
    float* csq_s = sm + SM_CSQ;
    int*   sidx  = (int*)(sm + SM_SIDX);
    float* xs_t  = zt;                       // phase A overlay (KT*XS_STRIDE = 4224)
    float* us    = zt + KT * XS_STRIDE;      // phase A overlay (KT*64 = 2048) <= 8448

    const int tid = threadIdx.x;
    const int R0  = blockIdx.x * ROWS;
    const int ty  = tid >> 3;                // 0..15 -> rows ty*8..+7
    const int tx  = tid & 7;                 // 0..7  -> cols tx*8..+7

    const size_t Z_OFF   = (size_t)B * DDIM;
    const size_t ZQ_OFF  = Z_OFF + (size_t)B * KLAT;
    const size_t IDX_OFF = ZQ_OFF + (size_t)B * KLAT;

    // ---------------- Phase A: z tile = x_tile @ U (FFMA2) ----------------
    u64 acc2[8][4];                          // acc2[i][p] = (z[i][2p], z[i][2p+1])
    #pragma unroll
    for (int i = 0; i < 8; i++)
        #pragma unroll
        for (int p = 0; p < 4; p++) acc2[i][p] = 0ull;

    const float4* x4 = (const float4*)x;
    const float4* U4 = (const float4*)U;

    for (int kk = 0; kk < DDIM; kk += KT) {
        #pragma unroll
        for (int j = 0; j < 8; j++) {
            int l4  = j * NTHR + tid;        // 0..1023
            int row = l4 >> 3;               // 0..127
            int k4  = l4 & 7;                // 0..7
            float4 v = x4[(size_t)(R0 + row) * (DDIM / 4) + (kk >> 2) + k4];
            xs_t[(4 * k4 + 0) * XS_STRIDE + row] = v.x;
            xs_t[(4 * k4 + 1) * XS_STRIDE + row] = v.y;
            xs_t[(4 * k4 + 2) * XS_STRIDE + row] = v.z;
            xs_t[(4 * k4 + 3) * XS_STRIDE + row] = v.w;
        }
        #pragma unroll
        for (int j = 0; j < 4; j++) {
            int l4 = j * NTHR + tid;         // 0..511
            int kr = l4 >> 4;                // 0..31
            int c4 = l4 & 15;                // 0..15
            ((float4*)us)[kr * 16 + c4] = U4[(kk + kr) * 16 + c4];
        }
        __syncthreads();
        #pragma unroll
        for (int k = 0; k < KT; k++) {
            float4 a0 = *(const float4*)&xs_t[k * XS_STRIDE + ty * 8];
            float4 a1 = *(const float4*)&xs_t[k * XS_STRIDE + ty * 8 + 4];
            ulonglong2 b01 = *(const ulonglong2*)&us[k * 64 + tx * 8];
            ulonglong2 b23 = *(const ulonglong2*)&us[k * 64 + tx * 8 + 4];
            u64 bp[4] = {b01.x, b01.y, b23.x, b23.y};
            float a[8] = {a0.x, a0.y, a0.z, a0.w, a1.x, a1.y, a1.z, a1.w};
            #pragma unroll
            for (int i = 0; i < 8; i++) {
                u64 ad = pk2(a[i], a[i]);
                #pragma unroll
                for (int p = 0; p < 4; p++) ffma2(acc2[i][p], ad, bp[p]);
            }
        }
        __syncthreads();
    }

    // z output straight from accumulators (coalesced float4 STG), and zt for phase B.
    {
        float4* oz = (float4*)(out + Z_OFF);
        #pragma unroll
        for (int i = 0; i < 8; i++) {
            int row = ty * 8 + i;
            float2 v0 = upk2(acc2[i][0]);
            float2 v1 = upk2(acc2[i][1]);
            float2 v2 = upk2(acc2[i][2]);
            float2 v3 = upk2(acc2[i][3]);
            float4 lo = make_float4(v0.x, v0.y, v1.x, v1.y);
            float4 hi = make_float4(v2.x, v2.y, v3.x, v3.y);
            oz[(size_t)(R0 + row) * 16 + tx * 2]     = lo;
            oz[(size_t)(R0 + row) * 16 + tx * 2 + 1] = hi;
            zt[(tx * 8 + 0) * ZT_STRIDE + row] = v0.x;
            zt[(tx * 8 + 1) * ZT_STRIDE + row] = v0.y;
            zt[(tx * 8 + 2) * ZT_STRIDE + row] = v1.x;
            zt[(tx * 8 + 3) * ZT_STRIDE + row] = v1.y;
            zt[(tx * 8 + 4) * ZT_STRIDE + row] = v2.x;
            zt[(tx * 8 + 5) * ZT_STRIDE + row] = v2.y;
            zt[(tx * 8 + 6) * ZT_STRIDE + row] = v3.x;
            zt[(tx * 8 + 7) * ZT_STRIDE + row] = v3.y;
        }
    }
    __syncthreads();

    // ---------------- Phase B: scores = z @ cb^T, 8x8 register tile (FFMA2) ----------------
    float best[8];
    int   bidx[8];
    #pragma unroll
    for (int i = 0; i < 8; i++) { best[i] = 3.4e38f; bidx[i] = 0; }

    const float4* cb4 = (const float4*)cb;

    for (int ct = 0; ct < NCODE; ct += CN) {
        // Load code tile transposed: cb[ct+c][k] -> cs[k][c]
        #pragma unroll
        for (int j = 0; j < 8; j++) {
            int l4 = j * NTHR + tid;         // 0..1023
            int c  = l4 >> 4;                // 0..63
            int k4 = l4 & 15;                // 0..15
            float4 v = cb4[(size_t)(ct + c) * 16 + k4];
            cs[(4 * k4 + 0) * CS_STRIDE + c] = v.x;
            cs[(4 * k4 + 1) * CS_STRIDE + c] = v.y;
            cs[(4 * k4 + 2) * CS_STRIDE + c] = v.z;
            cs[(4 * k4 + 3) * CS_STRIDE + c] = v.w;
        }
        if (tid < CN) csq_s[tid] = g_csq[ct + tid];
        __syncthreads();

        u64 dot2[8][4];
        #pragma unroll
        for (int i = 0; i < 8; i++)
            #pragma unroll
            for (int p = 0; p < 4; p++) dot2[i][p] = 0ull;

        #pragma unroll 4
        for (int k = 0; k < KLAT; k++) {
            float4 a0 = *(const float4*)&zt[k * ZT_STRIDE + ty * 8];
            float4 a1 = *(const float4*)&zt[k * ZT_STRIDE + ty * 8 + 4];
            ulonglong2 b01 = *(const ulonglong2*)&cs[k * CS_STRIDE + tx * 8];
            ulonglong2 b23 = *(const ulonglong2*)&cs[k * CS_STRIDE + tx * 8 + 4];
            u64 bp[4] = {b01.x, b01.y, b23.x, b23.y};
            float a[8] = {a0.x, a0.y, a0.z, a0.w, a1.x, a1.y, a1.z, a1.w};
            #pragma unroll
            for (int i = 0; i < 8; i++) {
                u64 ad = pk2(a[i], a[i]);
                #pragma unroll
                for (int p = 0; p < 4; p++) ffma2(dot2[i][p], ad, bp[p]);
            }
        }

        // score = csq - 2*dot; running first-min per row (thread-local codes ascending)
        #pragma unroll
        for (int p = 0; p < 4; p++) {
            float cq0 = csq_s[tx * 8 + 2 * p];
            float cq1 = csq_s[tx * 8 + 2 * p + 1];
            int code0 = ct + tx * 8 + 2 * p;
            #pragma unroll
            for (int i = 0; i < 8; i++) {
                float2 d = upk2(dot2[i][p]);
                float s0 = fmaf(-2.f, d.x, cq0);
                float s1 = fmaf(-2.f, d.y, cq1);
                if (s0 < best[i]) { best[i] = s0; bidx[i] = code0; }
                if (s1 < best[i]) { best[i] = s1; bidx[i] = code0 + 1; }
            }
        }
        __syncthreads();
    }

    // Cross-tx reduction (8 consecutive lanes share ty); tie-break toward lower index.
    #pragma unroll
    for (int i = 0; i < 8; i++) {
        float s = best[i];
        int   ix = bidx[i];
        #pragma unroll
        for (int off = 4; off > 0; off >>= 1) {
            float s2 = __shfl_down_sync(0xffffffffu, s, off, 8);
            int  ix2 = __shfl_down_sync(0xffffffffu, ix, off, 8);
            if (s2 < s || (s2 == s && ix2 < ix)) { s = s2; ix = ix2; }
        }
        if (tx == 0) sidx[ty * 8 + i] = ix;
    }
    __syncthreads();

    // ---------------- Phase C: outputs [x_recon | z_q_ste | indices] ----------------
    out[IDX_OFF + R0 + tid] = (float)sidx[tid];

    const int w = tid >> 5, lane = tid & 31;   // 4 warps x 32 rows
    const float2* cb2  = (const float2*)cb;
    const float4* dec4 = (const float4*)g_dec;
    float2* ozq = (float2*)(out + ZQ_OFF);
    float4* ox  = (float4*)out;
    for (int r = 0; r < 32; r++) {
        int row = w * 32 + r;
        int idx = sidx[row];
        float2 zv;
        zv.x = zt[(2 * lane)     * ZT_STRIDE + row];
        zv.y = zt[(2 * lane + 1) * ZT_STRIDE + row];
        float2 cv = cb2[(size_t)idx * (KLAT / 2) + lane];
        float2 o;
        o.x = zv.x + (cv.x - zv.x);          // STE numerics: z + (z_q - z)
        o.y = zv.y + (cv.y - zv.y);
        ozq[(size_t)(R0 + row) * (KLAT / 2) + lane] = o;
        #pragma unroll
        for (int j = 0; j < 4; j++)
            ox[(size_t)(R0 + row) * (DDIM / 4) + j * 32 + lane] =
                dec4[(size_t)idx * (DDIM / 4) + j * 32 + lane];
    }
}

extern "C" void kernel_launch(void* const* d_in, const int* in_sizes, int n_in,
                              void* d_out, int out_size) {
    // Identify inputs by element count: U_k = 512*64, codebook = 1024*64, x = B*512.
    const float *x = 0, *U = 0, *cb = 0;
    int xsize = 0;
    for (int i = 0; i < n_in; i++) {
        if (in_sizes[i] == DDIM * KLAT)       U  = (const float*)d_in[i];
        else if (in_sizes[i] == NCODE * KLAT) cb = (const float*)d_in[i];
        else { x = (const float*)d_in[i]; xsize = in_sizes[i]; }
    }
    float* out = (float*)d_out;
    const int B = xsize / DDIM;

    const int smem_bytes = SM_TOTAL * (int)sizeof(float);
    cudaFuncSetAttribute(vqvae_main, cudaFuncAttributeMaxDynamicSharedMemorySize, smem_bytes);

    prep_kernel<<<NCODE, 128>>>(U, cb);
    vqvae_main<<<B / ROWS, NTHR, smem_bytes>>>(x, U, cb, out, B);
}

// round 7
// speedup vs baseline: 1.6622x; 1.0051x over previous
#include <cuda_runtime.h>

#define DDIM   512
#define KLAT   64
#define NCODE  1024
#define ROWS   128      // rows per block
#define NTHR   128      // threads per block
#define KT     32       // k-tile for phase A
#define CN     64       // codes per tile for phase B
#define XS_STRIDE 132   // padded stride for transposed x tile (phase A overlay)
#define ZT_STRIDE 132   // padded stride for z tile, transposed [k][row]
#define CS_STRIDE 68    // padded stride for transposed code tile [k][code]

// Scratch: decoded codebook (codebook @ U_k^T) and per-code squared norms.
__device__ float g_dec[NCODE * DDIM];
__device__ float g_csq[NCODE];

// ---- packed f32x2 helpers (Blackwell FFMA2 path, PTX-only) ----
typedef unsigned long long u64;
static __device__ __forceinline__ u64 pk2(float x, float y) {
    u64 r;
    asm("mov.b64 %0, {%1, %2};" : "=l"(r) : "f"(x), "f"(y));
    return r;
}
static __device__ __forceinline__ float2 upk2(u64 v) {
    float2 f;
    asm("mov.b64 {%0, %1}, %2;" : "=f"(f.x), "=f"(f.y) : "l"(v));
    return f;
}
static __device__ __forceinline__ void ffma2(u64 &d, u64 a, u64 b) {
    asm("fma.rn.f32x2 %0, %1, %2, %0;" : "+l"(d) : "l"(a), "l"(b));
}

// Prep: g_dec[c][d] = sum_k codebook[c][k] * U[d][k];  g_csq[c] = ||codebook[c]||^2
__global__ void prep_kernel(const float* __restrict__ U, const float* __restrict__ cb) {
    __shared__ float code[KLAT];
    const int c = blockIdx.x;
    const int tid = threadIdx.x;   // 128 threads
    if (tid < KLAT / 4)
        ((float4*)code)[tid] = ((const float4*)(cb + c * KLAT))[tid];
    __syncthreads();
    if (tid == 0) {
        float s = 0.f;
        #pragma unroll
        for (int k = 0; k < KLAT; k++) s = fmaf(code[k], code[k], s);
        g_csq[c] = s;
    }
    #pragma unroll
    for (int i = 0; i < 4; i++) {
        const int d = tid + i * 128;
        const float4* u4 = (const float4*)(U + d * KLAT);
        float s = 0.f;
        #pragma unroll
        for (int q = 0; q < KLAT / 4; q++) {
            float4 u = u4[q];
            float4 cv = ((const float4*)code)[q];
            s = fmaf(u.x, cv.x, s);
            s = fmaf(u.y, cv.y, s);
            s = fmaf(u.z, cv.z, s);
            s = fmaf(u.w, cv.w, s);
        }
        g_dec[c * DDIM + d] = s;
    }
}

// Shared memory layout (floats). zt/cs get ONE EXTRA k-row so the software
// pipeline can prefetch k+1 unconditionally (dead data, never used in math).
//   zt   [0, 8580)           z transposed [k][row], 65 rows (phase A overlays)
//   cs   [8580, 13000)       code tile transposed [k][code], 65 rows
//   csq  [13000, 13064)
//   sidx [13064, 13192)
#define SM_ZT   0
#define SM_CS   8580
#define SM_CSQ  13000
#define SM_SIDX 13064
#define SM_TOTAL 13192

__global__ void __launch_bounds__(NTHR, 3)
vqvae_main(const float* __restrict__ x,
           const float* __restrict__ U,
           const float* __restrict__ cb,
           float* __restrict__ out,
           int B)
{
    extern __shared__ float sm[];
    float* zt    = sm + SM_ZT;
    float* cs    = sm + SM_CS;
    float* csq_s = sm + SM_CSQ;
    int*   sidx  = (int*)(sm + SM_SIDX);
    // Phase A overlay inside zt region: xs_t 33*132=4356, us 33*64=2112 (<= 8580)
    float* xs_t  = zt;
    float* us    = zt + (KT + 1) * XS_STRIDE;

    const int tid = threadIdx.x;
    const int R0  = blockIdx.x * ROWS;
    const int ty  = tid >> 3;                // 0..15 -> rows ty*8..+7
    const int tx  = tid & 7;                 // 0..7  -> cols tx*8..+7

    const size_t Z_OFF   = (size_t)B * DDIM;
    const size_t ZQ_OFF  = Z_OFF + (size_t)B * KLAT;
    const size_t IDX_OFF = ZQ_OFF + (size_t)B * KLAT;

    // ---------------- Phase A: z tile = x_tile @ U (FFMA2, pipelined) ----------------
    u64 acc2[8][4];
    #pragma unroll
    for (int i = 0; i < 8; i++)
        #pragma unroll
        for (int p = 0; p < 4; p++) acc2[i][p] = 0ull;

    const float4* x4 = (const float4*)x;
    const float4* U4 = (const float4*)U;

    for (int kk = 0; kk < DDIM; kk += KT) {
        #pragma unroll
        for (int j = 0; j < 8; j++) {
            int l4  = j * NTHR + tid;        // 0..1023
            int row = l4 >> 3;               // 0..127
            int k4  = l4 & 7;                // 0..7
            float4 v = x4[(size_t)(R0 + row) * (DDIM / 4) + (kk >> 2) + k4];
            xs_t[(4 * k4 + 0) * XS_STRIDE + row] = v.x;
            xs_t[(4 * k4 + 1) * XS_STRIDE + row] = v.y;
            xs_t[(4 * k4 + 2) * XS_STRIDE + row] = v.z;
            xs_t[(4 * k4 + 3) * XS_STRIDE + row] = v.w;
        }
        #pragma unroll
        for (int j = 0; j < 4; j++) {
            int l4 = j * NTHR + tid;         // 0..511
            int kr = l4 >> 4;                // 0..31
            int c4 = l4 & 15;                // 0..15
            ((float4*)us)[kr * 16 + c4] = U4[(kk + kr) * 16 + c4];
        }
        __syncthreads();

        // software-pipelined inner loop: prefetch k+1 while computing k
        float4 na0 = *(const float4*)&xs_t[ty * 8];
        float4 na1 = *(const float4*)&xs_t[ty * 8 + 4];
        ulonglong2 nb01 = *(const ulonglong2*)&us[tx * 8];
        ulonglong2 nb23 = *(const ulonglong2*)&us[tx * 8 + 4];
        #pragma unroll 8
        for (int k = 0; k < KT; k++) {
            float4 a0 = na0, a1 = na1;
            ulonglong2 b01 = nb01, b23 = nb23;
            na0  = *(const float4*)&xs_t[(k + 1) * XS_STRIDE + ty * 8];
            na1  = *(const float4*)&xs_t[(k + 1) * XS_STRIDE + ty * 8 + 4];
            nb01 = *(const ulonglong2*)&us[(k + 1) * 64 + tx * 8];
            nb23 = *(const ulonglong2*)&us[(k + 1) * 64 + tx * 8 + 4];
            u64 bp[4] = {b01.x, b01.y, b23.x, b23.y};
            float a[8] = {a0.x, a0.y, a0.z, a0.w, a1.x, a1.y, a1.z, a1.w};
            #pragma unroll
            for (int i = 0; i < 8; i++) {
                u64 ad = pk2(a[i], a[i]);
                #pragma unroll
                for (int p = 0; p < 4; p++) ffma2(acc2[i][p], ad, bp[p]);
            }
        }
        __syncthreads();
    }

    // z output straight from accumulators (coalesced float4 STG), and zt for phase B.
    {
        float4* oz = (float4*)(out + Z_OFF);
        #pragma unroll
        for (int i = 0; i < 8; i++) {
            int row = ty * 8 + i;
            float2 v0 = upk2(acc2[i][0]);
            float2 v1 = upk2(acc2[i][1]);
            float2 v2 = upk2(acc2[i][2]);
            float2 v3 = upk2(acc2[i][3]);
            float4 lo = make_float4(v0.x, v0.y, v1.x, v1.y);
            float4 hi = make_float4(v2.x, v2.y, v3.x, v3.y);
            oz[(size_t)(R0 + row) * 16 + tx * 2]     = lo;
            oz[(size_t)(R0 + row) * 16 + tx * 2 + 1] = hi;
            zt[(tx * 8 + 0) * ZT_STRIDE + row] = v0.x;
            zt[(tx * 8 + 1) * ZT_STRIDE + row] = v0.y;
            zt[(tx * 8 + 2) * ZT_STRIDE + row] = v1.x;
            zt[(tx * 8 + 3) * ZT_STRIDE + row] = v1.y;
            zt[(tx * 8 + 4) * ZT_STRIDE + row] = v2.x;
            zt[(tx * 8 + 5) * ZT_STRIDE + row] = v2.y;
            zt[(tx * 8 + 6) * ZT_STRIDE + row] = v3.x;
            zt[(tx * 8 + 7) * ZT_STRIDE + row] = v3.y;
        }
    }
    __syncthreads();

    // ---------------- Phase B: scores = z @ cb^T, 8x8 tile (FFMA2, pipelined) ----------------
    float best[8];
    int   bidx[8];
    #pragma unroll
    for (int i = 0; i < 8; i++) { best[i] = 3.4e38f; bidx[i] = 0; }

    const float4* cb4 = (const float4*)cb;

    for (int ct = 0; ct < NCODE; ct += CN) {
        // Load code tile transposed: cb[ct+c][k] -> cs[k][c]
        #pragma unroll
        for (int j = 0; j < 8; j++) {
            int l4 = j * NTHR + tid;         // 0..1023
            int c  = l4 >> 4;                // 0..63
            int k4 = l4 & 15;                // 0..15
            float4 v = cb4[(size_t)(ct + c) * 16 + k4];
            cs[(4 * k4 + 0) * CS_STRIDE + c] = v.x;
            cs[(4 * k4 + 1) * CS_STRIDE + c] = v.y;
            cs[(4 * k4 + 2) * CS_STRIDE + c] = v.z;
            cs[(4 * k4 + 3) * CS_STRIDE + c] = v.w;
        }
        if (tid < CN) csq_s[tid] = g_csq[ct + tid];
        __syncthreads();

        u64 dot2[8][4];
        #pragma unroll
        for (int i = 0; i < 8; i++)
            #pragma unroll
            for (int p = 0; p < 4; p++) dot2[i][p] = 0ull;

        float4 na0 = *(const float4*)&zt[ty * 8];
        float4 na1 = *(const float4*)&zt[ty * 8 + 4];
        ulonglong2 nb01 = *(const ulonglong2*)&cs[tx * 8];
        ulonglong2 nb23 = *(const ulonglong2*)&cs[tx * 8 + 4];
        #pragma unroll 8
        for (int k = 0; k < KLAT; k++) {
            float4 a0 = na0, a1 = na1;
            ulonglong2 b01 = nb01, b23 = nb23;
            na0  = *(const float4*)&zt[(k + 1) * ZT_STRIDE + ty * 8];
            na1  = *(const float4*)&zt[(k + 1) * ZT_STRIDE + ty * 8 + 4];
            nb01 = *(const ulonglong2*)&cs[(k + 1) * CS_STRIDE + tx * 8];
            nb23 = *(const ulonglong2*)&cs[(k + 1) * CS_STRIDE + tx * 8 + 4];
            u64 bp[4] = {b01.x, b01.y, b23.x, b23.y};
            float a[8] = {a0.x, a0.y, a0.z, a0.w, a1.x, a1.y, a1.z, a1.w};
            #pragma unroll
            for (int i = 0; i < 8; i++) {
                u64 ad = pk2(a[i], a[i]);
                #pragma unroll
                for (int p = 0; p < 4; p++) ffma2(dot2[i][p], ad, bp[p]);
            }
        }

        // score = csq - 2*dot; running first-min per row (thread-local codes ascending)
        #pragma unroll
        for (int p = 0; p < 4; p++) {
            float cq0 = csq_s[tx * 8 + 2 * p];
            float cq1 = csq_s[tx * 8 + 2 * p + 1];
            int code0 = ct + tx * 8 + 2 * p;
            #pragma unroll
            for (int i = 0; i < 8; i++) {
                float2 d = upk2(dot2[i][p]);
                float s0 = fmaf(-2.f, d.x, cq0);
                float s1 = fmaf(-2.f, d.y, cq1);
                if (s0 < best[i]) { best[i] = s0; bidx[i] = code0; }
                if (s1 < best[i]) { best[i] = s1; bidx[i] = code0 + 1; }
            }
        }
        __syncthreads();
    }

    // Cross-tx reduction (8 consecutive lanes share ty); tie-break toward lower index.
    #pragma unroll
    for (int i = 0; i < 8; i++) {
        float s = best[i];
        int   ix = bidx[i];
        #pragma unroll
        for (int off = 4; off > 0; off >>= 1) {
            float s2 = __shfl_down_sync(0xffffffffu, s, off, 8);
            int  ix2 = __shfl_down_sync(0xffffffffu, ix, off, 8);
            if (s2 < s || (s2 == s && ix2 < ix)) { s = s2; ix = ix2; }
        }
        if (tx == 0) sidx[ty * 8 + i] = ix;
    }
    __syncthreads();

    // ---------------- Phase C: outputs [x_recon | z_q_ste | indices] ----------------
    out[IDX_OFF + R0 + tid] = (float)sidx[tid];

    const int w = tid >> 5, lane = tid & 31;   // 4 warps x 32 rows
    const float2* cb2  = (const float2*)cb;
    const float4* dec4 = (const float4*)g_dec;
    float2* ozq = (float2*)(out + ZQ_OFF);
    float4* ox  = (float4*)out;
    for (int r = 0; r < 32; r++) {
        int row = w * 32 + r;
        int idx = sidx[row];
        float2 zv;
        zv.x = zt[(2 * lane)     * ZT_STRIDE + row];
        zv.y = zt[(2 * lane + 1) * ZT_STRIDE + row];
        float2 cv = cb2[(size_t)idx * (KLAT / 2) + lane];
        float2 o;
        o.x = zv.x + (cv.x - zv.x);          // STE numerics: z + (z_q - z)
        o.y = zv.y + (cv.y - zv.y);
        ozq[(size_t)(R0 + row) * (KLAT / 2) + lane] = o;
        #pragma unroll
        for (int j = 0; j < 4; j++)
            ox[(size_t)(R0 + row) * (DDIM / 4) + j * 32 + lane] =
                dec4[(size_t)idx * (DDIM / 4) + j * 32 + lane];
    }
}

extern "C" void kernel_launch(void* const* d_in, const int* in_sizes, int n_in,
                              void* d_out, int out_size) {
    // Identify inputs by element count: U_k = 512*64, codebook = 1024*64, x = B*512.
    const float *x = 0, *U = 0, *cb = 0;
    int xsize = 0;
    for (int i = 0; i < n_in; i++) {
        if (in_sizes[i] == DDIM * KLAT)       U  = (const float*)d_in[i];
        else if (in_sizes[i] == NCODE * KLAT) cb = (const float*)d_in[i];
        else { x = (const float*)d_in[i]; xsize = in_sizes[i]; }
    }
    float* out = (float*)d_out;
    const int B = xsize / DDIM;

    const int smem_bytes = SM_TOTAL * (int)sizeof(float);
    cudaFuncSetAttribute(vqvae_main, cudaFuncAttributeMaxDynamicSharedMemorySize, smem_bytes);

    prep_kernel<<<NCODE, 128>>>(U, cb);
    vqvae_main<<<B / ROWS, NTHR, smem_bytes>>>(x, U, cb, out, B);
}